// round 14
// baseline (speedup 1.0000x reference)
#include <cuda_runtime.h>
#include <cuda_fp16.h>
#include <cstdint>

// LocalGConv fp16 MMA: 2 CTAs/SM for decoupled scheduling.
//   phase B (transposed): pre^T[o=16][v=48] = W_s^T @ x^T   (single fp16)
//   phase C (normal):     out[u=48][o=16] = adjcat @ pre    (single fp16)
// Tail order (critical): STG epilogue -> x convert -> group barrier.
// B=32768, V=43 (pad 48), DIN=DOUT=64, S=2.
// 256 threads = 8 warps = 2 groups per CTA; group owns one batch/iter; warp owns 16 o.

#define NT   256
#define GRID 2048
#define IT   8
#define NV   43

// SMEM word offsets (per CTA)
#define WT_OFF  0                     // W^T fp16: [s*64+o rows][36 words]
#define ADJ_OFF 4608                  // adj fp16: [48 u rows][52 words]
#define X_OFF   7104                  // [2 bufs][2 groups][48 rows][36 words] fp16
#define XW      1728
#define STG_OFF (X_OFF + 4 * XW)      // fp32 stage: [2 groups][2752 words]
#define STGW    2752
#define SMEM_WORDS (STG_OFF + 2 * STGW)
#define SMEM_BYTES (SMEM_WORDS * 4)   // 78,080 B  (x2 CTAs = 156 KB/SM)

static __device__ __forceinline__ void mma16(float* d, const uint32_t* a, const uint32_t* b) {
    asm volatile(
        "mma.sync.aligned.m16n8k16.row.col.f32.f16.f16.f32 "
        "{%0,%1,%2,%3},{%4,%5,%6,%7},{%8,%9},{%0,%1,%2,%3};"
        : "+f"(d[0]), "+f"(d[1]), "+f"(d[2]), "+f"(d[3])
        : "r"(a[0]), "r"(a[1]), "r"(a[2]), "r"(a[3]), "r"(b[0]), "r"(b[1]));
}
static __device__ __forceinline__ void ldsm4(uint32_t* d, uint32_t addr) {
    asm volatile("ldmatrix.sync.aligned.m8n8.x4.shared.b16 {%0,%1,%2,%3}, [%4];"
        : "=r"(d[0]), "=r"(d[1]), "=r"(d[2]), "=r"(d[3]) : "r"(addr));
}
static __device__ __forceinline__ uint32_t su32(const void* p) {
    uint32_t a;
    asm("{ .reg .u64 t; cvta.to.shared.u64 t, %1; cvt.u32.u64 %0, t; }" : "=r"(a) : "l"(p));
    return a;
}
static __device__ __forceinline__ uint32_t f16x2(float hi, float lo) {
    uint32_t d;
    asm("cvt.rn.f16x2.f32 %0, %1, %2;" : "=r"(d) : "f"(hi), "f"(lo));
    return d;
}
static __device__ __forceinline__ void cpa16(uint32_t saddr, const void* g) {
    asm volatile("cp.async.ca.shared.global [%0], [%1], 16;" :: "r"(saddr), "l"(g));
}
#define CPA_COMMIT() asm volatile("cp.async.commit_group;" ::: "memory")
#define CPA_WAIT0()  asm volatile("cp.async.wait_group 0;" ::: "memory")
static __device__ __forceinline__ void barg(int bid) {
    asm volatile("bar.sync %0, 128;" :: "r"(bid) : "memory");
}

__global__ __launch_bounds__(NT, 2)
void lgconv_fp16(const float* __restrict__ gx, const float* __restrict__ gadj,
                 const float* __restrict__ gw, const float* __restrict__ gb,
                 float* __restrict__ gout)
{
    extern __shared__ uint32_t sm[];
    uint16_t* shw = (uint16_t*)sm;
    float* smf = (float*)sm;
    const uint32_t sb = su32(sm);
    const int tid = threadIdx.x, wid = tid >> 5, lane = tid & 31;
    const int g = lane >> 2, t = lane & 3;
    const int grp = wid >> 2, wo = wid & 3, gtid = tid & 127;
    const int q = lane >> 3, rr = lane & 7;

    // ldmatrix per-lane byte offsets
    const uint32_t aoffW = (uint32_t)(((wo * 16 + (q & 1) * 8 + rr) * 36 + (q >> 1) * 4) * 4);
    const uint32_t boffX = (uint32_t)((((q >> 1) * 8 + rr) * 36 + (q & 1) * 4) * 4);
    const uint32_t aoffA = (uint32_t)((((q & 1) * 8 + rr) * 52 + (q >> 1) * 4) * 4);

    // ---- prologue: W^T fp16, adj fp16 (zero-padded), x pad rows ----
    for (int i = tid; i < 2496; i += NT) sm[ADJ_OFF + i] = 0;
    for (int i = tid; i < 2 * 2 * 5 * 36; i += NT) {   // x pad rows 43..47, both bufs
        int bg = i / 180, r = i % 180;
        sm[X_OFF + bg * XW + (NV + r / 36) * 36 + (r % 36)] = 0;
    }
    for (int idx = tid; idx < 2 * 64 * 64; idx += NT) {
        int s = idx >> 12, i = (idx >> 6) & 63, o = idx & 63;
        __half hh = __float2half_rn(gw[idx]);
        shw[WT_OFF * 2 + (s * 64 + o) * 72 + i] = *(uint16_t*)&hh;
    }
    __syncthreads();
    for (int idx = tid; idx < 2 * NV * NV; idx += NT) {
        int s = idx / (NV * NV), r = idx % (NV * NV), u = r / NV, v = r % NV;
        __half h = __float2half_rn(gadj[idx]);
        shw[ADJ_OFF * 2 + u * 104 + s * 48 + v] = *(uint16_t*)&h;
    }
    float2 bb[2];
    #pragma unroll
    for (int oh = 0; oh < 2; ++oh)
        bb[oh] = *(const float2*)(gb + wo * 16 + oh * 8 + 2 * t);

    const uint32_t wt_b  = sb + WT_OFF * 4;
    const uint32_t adj_b = sb + ADJ_OFF * 4;
    const size_t bbase = (size_t)(blockIdx.x * 2 + grp) * IT;

    // ---- initial x load into buffer 0 ----
    {
        uint32_t* xg = sm + X_OFF + grp * XW;
        const float4* src = (const float4*)(gx + bbase * (NV * 64));
        for (int j = gtid; j < NV * 16; j += 128) {
            float4 f = src[j];
            uint32_t* dst = xg + (j >> 4) * 36 + (j & 15) * 2;
            dst[0] = f16x2(f.y, f.x);
            dst[1] = f16x2(f.w, f.z);
        }
    }
    __syncthreads();

    // ---- hoist W fragments: loop-invariant, loaded once ----
    uint32_t whf[4][2][4];
    #pragma unroll
    for (int kt = 0; kt < 4; ++kt)
        #pragma unroll
        for (int s = 0; s < 2; ++s)
            ldsm4(whf[kt][s], wt_b + (uint32_t)(s * 64 * 36 * 4) + kt * 32 + aoffW);

    const int bar = grp + 1;

    for (int it = 0; it < IT; ++it) {
        const size_t b = bbase + it;
        const int cur = it & 1, nxt = cur ^ 1;
        const uint32_t x_b = sb + (X_OFF + (cur * 2 + grp) * XW) * 4;
        const bool pf = (it + 1 < IT);

        // ---- issue cp.async prefetch of next x at iteration start ----
        if (pf) {
            const float4* srcn = (const float4*)(gx + (b + 1) * (NV * 64));
            const uint32_t st = sb + (STG_OFF + grp * STGW) * 4;
            #pragma unroll
            for (int j5 = 0; j5 < 6; ++j5) {
                int idx = gtid + j5 * 128;
                if (idx < NV * 16) cpa16(st + (uint32_t)idx * 16, srcn + idx);
            }
            CPA_COMMIT();
        }

        // ---- Phase B: pre^T[o][v] per support ----
        float accB[2][6][4];
        #pragma unroll
        for (int s = 0; s < 2; ++s)
            #pragma unroll
            for (int nt = 0; nt < 6; ++nt)
                #pragma unroll
                for (int j = 0; j < 4; ++j) accB[s][nt][j] = 0.f;

        #pragma unroll
        for (int kt = 0; kt < 4; ++kt) {
            uint32_t bx[3][4];
            #pragma unroll
            for (int nb = 0; nb < 3; ++nb)
                ldsm4(bx[nb], x_b + (uint32_t)(nb * 16 * 36 * 4) + kt * 32 + boffX);
            #pragma unroll
            for (int s = 0; s < 2; ++s)
                #pragma unroll
                for (int nt = 0; nt < 6; ++nt)
                    mma16(accB[s][nt], whf[kt][s], &bx[nt >> 1][(nt & 1) * 2]);
        }

        // ---- pack accB -> phase-C B-fragments (registers only) ----
        uint32_t pb[2][3][2][2];   // [s][vb][oh][b0,b1]
        #pragma unroll
        for (int s = 0; s < 2; ++s)
            #pragma unroll
            for (int vb = 0; vb < 3; ++vb) {
                const float* c = accB[s][2 * vb];
                const float* d = accB[s][2 * vb + 1];
                pb[s][vb][0][0] = f16x2(c[1], c[0]);
                pb[s][vb][1][0] = f16x2(c[3], c[2]);
                pb[s][vb][0][1] = f16x2(d[1], d[0]);
                pb[s][vb][1][1] = f16x2(d[3], d[2]);
            }

        // ---- Phase C: out[u][own o] = bias + adjcat @ pre ----
        float oc[3][2][4];
        #pragma unroll
        for (int mt = 0; mt < 3; ++mt)
            #pragma unroll
            for (int oh = 0; oh < 2; ++oh) {
                oc[mt][oh][0] = bb[oh].x; oc[mt][oh][1] = bb[oh].y;
                oc[mt][oh][2] = bb[oh].x; oc[mt][oh][3] = bb[oh].y;
            }
        #pragma unroll
        for (int s = 0; s < 2; ++s)
            #pragma unroll
            for (int vb = 0; vb < 3; ++vb) {
                const uint32_t kb = (uint32_t)(s * 3 + vb) * 32;
                uint32_t ba[3][4];
                #pragma unroll
                for (int mt = 0; mt < 3; ++mt)
                    ldsm4(ba[mt], adj_b + (uint32_t)(mt * 16 * 52 * 4) + kb + aoffA);
                #pragma unroll
                for (int mt = 0; mt < 3; ++mt)
                    #pragma unroll
                    for (int oh = 0; oh < 2; ++oh)
                        mma16(oc[mt][oh], ba[mt], pb[s][vb][oh]);
            }

        // ---- epilogue: relu + coalesced float2 stores (BEFORE barrier) ----
        {
            float* op = gout + b * (NV * 64) + wo * 16 + 2 * t;
            #pragma unroll
            for (int mt = 0; mt < 3; ++mt)
                #pragma unroll
                for (int oh = 0; oh < 2; ++oh) {
                    const int u0 = mt * 16 + g, u1 = u0 + 8;
                    *(float2*)(op + u0 * 64 + oh * 8) =
                        make_float2(fmaxf(oc[mt][oh][0], 0.f), fmaxf(oc[mt][oh][1], 0.f));
                    if (u1 < NV)
                        *(float2*)(op + u1 * 64 + oh * 8) =
                            make_float2(fmaxf(oc[mt][oh][2], 0.f), fmaxf(oc[mt][oh][3], 0.f));
                }
        }

        // ---- tail: convert own staged float4s -> fp16 buffer, then barrier ----
        if (pf) {
            CPA_WAIT0();   // own copies complete; each thread converts what it copied
            const float4* stf = (const float4*)(smf + STG_OFF + grp * STGW);
            uint32_t* xg = sm + X_OFF + (nxt * 2 + grp) * XW;
            #pragma unroll
            for (int j5 = 0; j5 < 6; ++j5) {
                int idx = gtid + j5 * 128;
                if (idx < NV * 16) {
                    float4 f = stf[idx];
                    uint32_t* dst = xg + (idx >> 4) * 36 + (idx & 15) * 2;
                    dst[0] = f16x2(f.y, f.x);
                    dst[1] = f16x2(f.w, f.z);
                }
            }
            barg(bar);
        }
    }
}

extern "C" void kernel_launch(void* const* d_in, const int* in_sizes, int n_in,
                              void* d_out, int out_size) {
    const float* x   = (const float*)d_in[0];
    const float* adj = (const float*)d_in[1];
    const float* W   = (const float*)d_in[2];
    const float* b   = (const float*)d_in[3];
    float* out = (float*)d_out;

    cudaFuncSetAttribute(lgconv_fp16, cudaFuncAttributeMaxDynamicSharedMemorySize, SMEM_BYTES);
    lgconv_fp16<<<GRID, NT, SMEM_BYTES>>>(x, adj, W, b, out);
}

// round 15
// speedup vs baseline: 1.0159x; 1.0159x over previous
#include <cuda_runtime.h>
#include <cuda_fp16.h>
#include <cstdint>

// LocalGConv fp16 MMA: W-frag hoist, cp.async staging, rotated pipeline:
//   [cpa issue][phase B][pack][wait+convert+bar][phase C][STG epilogue]
// phase B (transposed): pre^T[o=16][v=48] = W_s^T @ x^T   (single fp16)
// phase C (normal):     out[u=48][o=16] = adjcat @ pre    (single fp16)
// B=32768, V=43 (pad 48), DIN=DOUT=64, S=2.
// 512 threads = 16 warps = 4 groups; group owns one batch/iter; warp owns 16 o.

#define NT   512
#define GRID 1024
#define IT   8
#define NV   43

// SMEM word offsets
#define WT_OFF  0                     // W^T fp16: [s*64+o rows][36 words]
#define ADJ_OFF 4608                  // adj fp16: [48 u rows][52 words]
#define X_OFF   7104                  // [2 bufs][4 groups][48 rows][36 words] fp16
#define XW      1728
#define STG_OFF (X_OFF + 8 * XW)      // fp32 stage: [4 groups][2752 words]
#define STGW    2752
#define SMEM_WORDS (STG_OFF + 4 * STGW)
#define SMEM_BYTES (SMEM_WORDS * 4)   // 127,744 B

static __device__ __forceinline__ void mma16(float* d, const uint32_t* a, const uint32_t* b) {
    asm volatile(
        "mma.sync.aligned.m16n8k16.row.col.f32.f16.f16.f32 "
        "{%0,%1,%2,%3},{%4,%5,%6,%7},{%8,%9},{%0,%1,%2,%3};"
        : "+f"(d[0]), "+f"(d[1]), "+f"(d[2]), "+f"(d[3])
        : "r"(a[0]), "r"(a[1]), "r"(a[2]), "r"(a[3]), "r"(b[0]), "r"(b[1]));
}
static __device__ __forceinline__ void ldsm4(uint32_t* d, uint32_t addr) {
    asm volatile("ldmatrix.sync.aligned.m8n8.x4.shared.b16 {%0,%1,%2,%3}, [%4];"
        : "=r"(d[0]), "=r"(d[1]), "=r"(d[2]), "=r"(d[3]) : "r"(addr));
}
static __device__ __forceinline__ uint32_t su32(const void* p) {
    uint32_t a;
    asm("{ .reg .u64 t; cvta.to.shared.u64 t, %1; cvt.u32.u64 %0, t; }" : "=r"(a) : "l"(p));
    return a;
}
static __device__ __forceinline__ uint32_t f16x2(float hi, float lo) {
    uint32_t d;
    asm("cvt.rn.f16x2.f32 %0, %1, %2;" : "=r"(d) : "f"(hi), "f"(lo));
    return d;
}
static __device__ __forceinline__ void cpa16(uint32_t saddr, const void* g) {
    asm volatile("cp.async.ca.shared.global [%0], [%1], 16;" :: "r"(saddr), "l"(g));
}
#define CPA_COMMIT() asm volatile("cp.async.commit_group;" ::: "memory")
#define CPA_WAIT0()  asm volatile("cp.async.wait_group 0;" ::: "memory")
static __device__ __forceinline__ void barg(int bid) {
    asm volatile("bar.sync %0, 128;" :: "r"(bid) : "memory");
}

__global__ __launch_bounds__(NT, 1)
void lgconv_fp16(const float* __restrict__ gx, const float* __restrict__ gadj,
                 const float* __restrict__ gw, const float* __restrict__ gb,
                 float* __restrict__ gout)
{
    extern __shared__ uint32_t sm[];
    uint16_t* shw = (uint16_t*)sm;
    float* smf = (float*)sm;
    const uint32_t sb = su32(sm);
    const int tid = threadIdx.x, wid = tid >> 5, lane = tid & 31;
    const int g = lane >> 2, t = lane & 3;
    const int grp = wid >> 2, wo = wid & 3, gtid = tid & 127;
    const int q = lane >> 3, rr = lane & 7;

    // ldmatrix per-lane byte offsets
    const uint32_t aoffW = (uint32_t)(((wo * 16 + (q & 1) * 8 + rr) * 36 + (q >> 1) * 4) * 4);
    const uint32_t boffX = (uint32_t)((((q >> 1) * 8 + rr) * 36 + (q & 1) * 4) * 4);
    const uint32_t aoffA = (uint32_t)((((q & 1) * 8 + rr) * 52 + (q >> 1) * 4) * 4);

    // ---- prologue: W^T fp16, adj fp16 (zero-padded), x pad rows ----
    for (int i = tid; i < 2496; i += NT) sm[ADJ_OFF + i] = 0;
    for (int i = tid; i < 2 * 4 * 5 * 36; i += NT) {   // x pad rows 43..47, both bufs
        int bg = i / 180, r = i % 180;
        sm[X_OFF + bg * XW + (NV + r / 36) * 36 + (r % 36)] = 0;
    }
    for (int idx = tid; idx < 2 * 64 * 64; idx += NT) {
        int s = idx >> 12, i = (idx >> 6) & 63, o = idx & 63;
        __half hh = __float2half_rn(gw[idx]);
        shw[WT_OFF * 2 + (s * 64 + o) * 72 + i] = *(uint16_t*)&hh;
    }
    __syncthreads();
    for (int idx = tid; idx < 2 * NV * NV; idx += NT) {
        int s = idx / (NV * NV), r = idx % (NV * NV), u = r / NV, v = r % NV;
        __half h = __float2half_rn(gadj[idx]);
        shw[ADJ_OFF * 2 + u * 104 + s * 48 + v] = *(uint16_t*)&h;
    }
    float2 bb[2];
    #pragma unroll
    for (int oh = 0; oh < 2; ++oh)
        bb[oh] = *(const float2*)(gb + wo * 16 + oh * 8 + 2 * t);

    const uint32_t wt_b  = sb + WT_OFF * 4;
    const uint32_t adj_b = sb + ADJ_OFF * 4;
    const size_t bbase = (size_t)(blockIdx.x * 4 + grp) * IT;

    // ---- initial x load into buffer 0 ----
    {
        uint32_t* xg = sm + X_OFF + grp * XW;
        const float4* src = (const float4*)(gx + bbase * (NV * 64));
        for (int j = gtid; j < NV * 16; j += 128) {
            float4 f = src[j];
            uint32_t* dst = xg + (j >> 4) * 36 + (j & 15) * 2;
            dst[0] = f16x2(f.y, f.x);
            dst[1] = f16x2(f.w, f.z);
        }
    }
    __syncthreads();

    // ---- hoist W fragments: loop-invariant, loaded once ----
    uint32_t whf[4][2][4];
    #pragma unroll
    for (int kt = 0; kt < 4; ++kt)
        #pragma unroll
        for (int s = 0; s < 2; ++s)
            ldsm4(whf[kt][s], wt_b + (uint32_t)(s * 64 * 36 * 4) + kt * 32 + aoffW);

    const int bar = grp + 1;

    for (int it = 0; it < IT; ++it) {
        const size_t b = bbase + it;
        const int cur = it & 1, nxt = cur ^ 1;
        const uint32_t x_b = sb + (X_OFF + (cur * 4 + grp) * XW) * 4;
        const bool pf = (it + 1 < IT);

        // ---- issue cp.async prefetch of next x at iteration start ----
        if (pf) {
            const float4* srcn = (const float4*)(gx + (b + 1) * (NV * 64));
            const uint32_t st = sb + (STG_OFF + grp * STGW) * 4;
            #pragma unroll
            for (int j5 = 0; j5 < 6; ++j5) {
                int idx = gtid + j5 * 128;
                if (idx < NV * 16) cpa16(st + (uint32_t)idx * 16, srcn + idx);
            }
            CPA_COMMIT();
        }

        // ---- Phase B: pre^T[o][v] per support ----
        float accB[2][6][4];
        #pragma unroll
        for (int s = 0; s < 2; ++s)
            #pragma unroll
            for (int nt = 0; nt < 6; ++nt)
                #pragma unroll
                for (int j = 0; j < 4; ++j) accB[s][nt][j] = 0.f;

        #pragma unroll
        for (int kt = 0; kt < 4; ++kt) {
            uint32_t bx[3][4];
            #pragma unroll
            for (int nb = 0; nb < 3; ++nb)
                ldsm4(bx[nb], x_b + (uint32_t)(nb * 16 * 36 * 4) + kt * 32 + boffX);
            #pragma unroll
            for (int s = 0; s < 2; ++s)
                #pragma unroll
                for (int nt = 0; nt < 6; ++nt)
                    mma16(accB[s][nt], whf[kt][s], &bx[nt >> 1][(nt & 1) * 2]);
        }

        // ---- pack accB -> phase-C B-fragments (registers only) ----
        uint32_t pb[2][3][2][2];   // [s][vb][oh][b0,b1]
        #pragma unroll
        for (int s = 0; s < 2; ++s)
            #pragma unroll
            for (int vb = 0; vb < 3; ++vb) {
                const float* c = accB[s][2 * vb];
                const float* d = accB[s][2 * vb + 1];
                pb[s][vb][0][0] = f16x2(c[1], c[0]);
                pb[s][vb][1][0] = f16x2(c[3], c[2]);
                pb[s][vb][0][1] = f16x2(d[1], d[0]);
                pb[s][vb][1][1] = f16x2(d[3], d[2]);
            }

        // ---- ROTATED TAIL: x(it+1) convert + group barrier BEFORE phase C ----
        // cur x-buffer is dead after phase B; phase C touches only adj + regs.
        if (pf) {
            CPA_WAIT0();   // own copies complete; each thread converts what it copied
            const float4* stf = (const float4*)(smf + STG_OFF + grp * STGW);
            uint32_t* xg = sm + X_OFF + (nxt * 4 + grp) * XW;
            #pragma unroll
            for (int j5 = 0; j5 < 6; ++j5) {
                int idx = gtid + j5 * 128;
                if (idx < NV * 16) {
                    float4 f = stf[idx];
                    uint32_t* dst = xg + (idx >> 4) * 36 + (idx & 15) * 2;
                    dst[0] = f16x2(f.y, f.x);
                    dst[1] = f16x2(f.w, f.z);
                }
            }
            barg(bar);
        }

        // ---- Phase C: out[u][own o] = bias + adjcat @ pre ----
        float oc[3][2][4];
        #pragma unroll
        for (int mt = 0; mt < 3; ++mt)
            #pragma unroll
            for (int oh = 0; oh < 2; ++oh) {
                oc[mt][oh][0] = bb[oh].x; oc[mt][oh][1] = bb[oh].y;
                oc[mt][oh][2] = bb[oh].x; oc[mt][oh][3] = bb[oh].y;
            }
        #pragma unroll
        for (int s = 0; s < 2; ++s)
            #pragma unroll
            for (int vb = 0; vb < 3; ++vb) {
                const uint32_t kb = (uint32_t)(s * 3 + vb) * 32;
                uint32_t ba[3][4];
                #pragma unroll
                for (int mt = 0; mt < 3; ++mt)
                    ldsm4(ba[mt], adj_b + (uint32_t)(mt * 16 * 52 * 4) + kb + aoffA);
                #pragma unroll
                for (int mt = 0; mt < 3; ++mt)
                    #pragma unroll
                    for (int oh = 0; oh < 2; ++oh)
                        mma16(oc[mt][oh], ba[mt], pb[s][vb][oh]);
            }

        // ---- epilogue: relu + coalesced float2 stores (drains into next iter) ----
        {
            float* op = gout + b * (NV * 64) + wo * 16 + 2 * t;
            #pragma unroll
            for (int mt = 0; mt < 3; ++mt)
                #pragma unroll
                for (int oh = 0; oh < 2; ++oh) {
                    const int u0 = mt * 16 + g, u1 = u0 + 8;
                    *(float2*)(op + u0 * 64 + oh * 8) =
                        make_float2(fmaxf(oc[mt][oh][0], 0.f), fmaxf(oc[mt][oh][1], 0.f));
                    if (u1 < NV)
                        *(float2*)(op + u1 * 64 + oh * 8) =
                            make_float2(fmaxf(oc[mt][oh][2], 0.f), fmaxf(oc[mt][oh][3], 0.f));
                }
        }
    }
}

extern "C" void kernel_launch(void* const* d_in, const int* in_sizes, int n_in,
                              void* d_out, int out_size) {
    const float* x   = (const float*)d_in[0];
    const float* adj = (const float*)d_in[1];
    const float* W   = (const float*)d_in[2];
    const float* b   = (const float*)d_in[3];
    float* out = (float*)d_out;

    cudaFuncSetAttribute(lgconv_fp16, cudaFuncAttributeMaxDynamicSharedMemorySize, SMEM_BYTES);
    lgconv_fp16<<<GRID, NT, SMEM_BYTES>>>(x, adj, W, b, out);
}